// round 3
// baseline (speedup 1.0000x reference)
#include <cuda_runtime.h>

// Problem constants (B=32, T=1024, N=2048)
#define BB 32
#define TT 1024
#define NN 2048
#define ALPHA 0.995f
#define VTH   2.0f

// Scratch (device globals -- no allocation allowed)
__device__ float g_ST[BB * TT];  // S transposed: [t][b]
__device__ float g_CT[BB * TT];  // c_t transposed
__device__ float g_VT[BB * TT];  // v_t transposed
__device__ float g_AT[BB * TT];  // a_t = v_t + q_t transposed
__device__ float g_V2[BB];       // sum of v_t^2 per batch

// ---------------------------------------------------------------------------
// Kernel 1: S[b,t] = x[b,t,:] . w   (row dot products), stored transposed.
// grid = 4096 CTAs x 8 rows each, block = 128 threads, float4 loads.
// ---------------------------------------------------------------------------
__global__ __launch_bounds__(128) void k_gemv(const float4* __restrict__ X4,
                                              const float4* __restrict__ W4) {
    __shared__ float red[4];
    const int tid = threadIdx.x;

    // w resident in registers, reused across 8 rows
    const float4 w0 = W4[tid];
    const float4 w1 = W4[128 + tid];
    const float4 w2 = W4[256 + tid];
    const float4 w3 = W4[384 + tid];

    const int base_row = blockIdx.x * 8;

#pragma unroll 1
    for (int rr = 0; rr < 8; rr++) {
        const int r = base_row + rr;                 // r = b*TT + t, < 32768
        const float4* xp = X4 + (size_t)r * (NN / 4);
        const float4 x0 = xp[tid];
        const float4 x1 = xp[128 + tid];
        const float4 x2 = xp[256 + tid];
        const float4 x3 = xp[384 + tid];

        float s = x0.x * w0.x + x0.y * w0.y + x0.z * w0.z + x0.w * w0.w
                + x1.x * w1.x + x1.y * w1.y + x1.z * w1.z + x1.w * w1.w
                + x2.x * w2.x + x2.y * w2.y + x2.z * w2.z + x2.w * w2.w
                + x3.x * w3.x + x3.y * w3.y + x3.z * w3.z + x3.w * w3.w;

        // warp reduce
#pragma unroll
        for (int o = 16; o > 0; o >>= 1)
            s += __shfl_xor_sync(0xFFFFFFFFu, s, o);
        if ((tid & 31) == 0) red[tid >> 5] = s;
        __syncthreads();
        if (tid == 0) {
            const float tot = red[0] + red[1] + red[2] + red[3];
            const int b = r >> 10;
            const int t = r & (TT - 1);
            g_ST[t * BB + b] = tot;
        }
        __syncthreads();
    }
}

// ---------------------------------------------------------------------------
// Kernel 2: scalar scans. One warp, lane = batch.
//   forward : v_t = a*v + s_t - vth*z_{t-1}; z_t = v_t > vth
//             c_t = s_t - v_t*(w.w);  V2 += v_t^2
//   backward: a_t = v_t + q_t;  q_{t-1} = c_t + alpha*q_t
// Writes v_seq, z_seq directly into d_out.
// ---------------------------------------------------------------------------
__global__ __launch_bounds__(32) void k_scan(const float* __restrict__ w,
                                             float* __restrict__ out) {
    const int lane = threadIdx.x;  // 0..31 == batch index

    // w . w (redundant across lanes after reduce)
    float ww = 0.0f;
#pragma unroll 8
    for (int i = lane; i < NN; i += 32) ww += w[i] * w[i];
#pragma unroll
    for (int o = 16; o > 0; o >>= 1)
        ww += __shfl_xor_sync(0xFFFFFFFFu, ww, o);

    float* vout = out + lane * TT;
    float* zout = out + BB * TT + lane * TT;

    // ---- forward scan ----
    float v = 0.0f;
    float v2 = 0.0f;
#pragma unroll 4
    for (int t = 0; t < TT; t++) {
        const float s = g_ST[t * BB + lane];
        // z_{t-1} = (v > VTH): fold threshold subtraction into a select so the
        // loop-carried chain is FSETP -> FSEL -> FFMA.
        const float inj = (v > VTH) ? (s - VTH) : s;
        v = ALPHA * v + inj;
        const float z = (v > VTH) ? 1.0f : 0.0f;
        vout[t] = v;
        zout[t] = z;
        g_VT[t * BB + lane] = v;
        g_CT[t * BB + lane] = s - v * ww;
        v2 += v * v;
    }
    g_V2[lane] = v2;

    // ---- backward scan ----
    float q = 0.0f;
#pragma unroll 4
    for (int t = TT - 1; t >= 0; t--) {
        const float a = g_VT[t * BB + lane] + q;   // a_t = v_t + q_t
        g_AT[t * BB + lane] = a;
        q = g_CT[t * BB + lane] + ALPHA * q;       // q_{t-1}
    }
}

// ---------------------------------------------------------------------------
// Kernel 3: grad[b,n] = sum_t a[b,t] * x[b,t,n]  -  V2[b] * w[n]
// grid = (4 column-chunks, 32 batches), block = 128 threads (float4 each,
// 512 columns per CTA). Streams 1024 rows with a_t broadcast from smem.
// ---------------------------------------------------------------------------
__global__ __launch_bounds__(128) void k_grad(const float4* __restrict__ X4,
                                              const float4* __restrict__ W4,
                                              float* __restrict__ out) {
    __shared__ float sa[TT];
    const int tid   = threadIdx.x;   // 0..127
    const int chunk = blockIdx.x;    // 0..3
    const int b     = blockIdx.y;    // 0..31

    for (int t = tid; t < TT; t += 128) sa[t] = g_AT[t * BB + b];
    __syncthreads();

    const int col4 = chunk * 128 + tid;  // float4 column index, 0..511
    const float4* xp = X4 + (size_t)b * TT * (NN / 4) + col4;

    float4 acc = make_float4(0.f, 0.f, 0.f, 0.f);
#pragma unroll 8
    for (int t = 0; t < TT; t++) {
        const float a = sa[t];
        const float4 x = xp[(size_t)t * (NN / 4)];
        acc.x += a * x.x;
        acc.y += a * x.y;
        acc.z += a * x.z;
        acc.w += a * x.w;
    }

    const float v2 = g_V2[b];
    const float4 wv = W4[col4];
    float4 g;
    g.x = acc.x - v2 * wv.x;
    g.y = acc.y - v2 * wv.y;
    g.z = acc.z - v2 * wv.z;
    g.w = acc.w - v2 * wv.w;

    float4* gout = (float4*)(out + 2 * BB * TT);
    gout[(size_t)b * (NN / 4) + col4] = g;
}

// ---------------------------------------------------------------------------
extern "C" void kernel_launch(void* const* d_in, const int* in_sizes, int n_in,
                              void* d_out, int out_size) {
    const float* x = (const float*)d_in[0];
    const float* w = (const float*)d_in[1];
    // Defensive: metadata order should be (x, w); swap if sizes say otherwise.
    if (n_in >= 2 && in_sizes[0] == NN && in_sizes[1] != NN) {
        const float* tmp = x; x = w; w = tmp;
    }
    float* out = (float*)d_out;

    k_gemv<<<4096, 128>>>((const float4*)x, (const float4*)w);
    k_scan<<<1, 32>>>(w, out);
    k_grad<<<dim3(4, 32), 128>>>((const float4*)x, (const float4*)w, out);
}

// round 4
// speedup vs baseline: 3.0158x; 3.0158x over previous
#include <cuda_runtime.h>

// Problem constants (B=32, T=1024, N=2048)
#define BB 32
#define TT 1024
#define NN 2048
#define ALPHA 0.995f
#define VTH   2.0f

// Scratch (device globals -- no allocation allowed)
__device__ float g_S[BB * TT];   // S[b][t] = x[b,t,:] . w
__device__ float g_A[BB * TT];   // a[b][t] = v_t + q_t
__device__ float g_V2[BB];       // sum of v_t^2 per batch

// ---------------------------------------------------------------------------
// Kernel 1: S[b,t] = x[b,t,:] . w   (row dot products), [b][t] layout.
// grid = 4096 CTAs x 8 rows each, block = 128 threads, float4 loads.
// Measured at ~6.1 TB/s (LTS cap) -- leave unchanged except output layout.
// ---------------------------------------------------------------------------
__global__ __launch_bounds__(128) void k_gemv(const float4* __restrict__ X4,
                                              const float4* __restrict__ W4) {
    __shared__ float red[4];
    const int tid = threadIdx.x;

    // w resident in registers, reused across 8 rows
    const float4 w0 = W4[tid];
    const float4 w1 = W4[128 + tid];
    const float4 w2 = W4[256 + tid];
    const float4 w3 = W4[384 + tid];

    const int base_row = blockIdx.x * 8;

#pragma unroll 1
    for (int rr = 0; rr < 8; rr++) {
        const int r = base_row + rr;                 // r = b*TT + t, < 32768
        const float4* xp = X4 + (size_t)r * (NN / 4);
        const float4 x0 = xp[tid];
        const float4 x1 = xp[128 + tid];
        const float4 x2 = xp[256 + tid];
        const float4 x3 = xp[384 + tid];

        float s = x0.x * w0.x + x0.y * w0.y + x0.z * w0.z + x0.w * w0.w
                + x1.x * w1.x + x1.y * w1.y + x1.z * w1.z + x1.w * w1.w
                + x2.x * w2.x + x2.y * w2.y + x2.z * w2.z + x2.w * w2.w
                + x3.x * w3.x + x3.y * w3.y + x3.z * w3.z + x3.w * w3.w;

        // warp reduce
#pragma unroll
        for (int o = 16; o > 0; o >>= 1)
            s += __shfl_xor_sync(0xFFFFFFFFu, s, o);
        if ((tid & 31) == 0) red[tid >> 5] = s;
        __syncthreads();
        if (tid == 0) g_S[r] = s * 0.0f + red[0] + red[1] + red[2] + red[3];
        __syncthreads();
    }
}

// ---------------------------------------------------------------------------
// Kernel 2: per-batch scalar scans, one CTA per batch, scan runs from SMEM.
//   forward : v_t = a*v + s_t - VTH*z_{t-1};  (v overwrites s in smem)
//   backward: c_t = v_t - a*v_{t-1} + VTH*z_{t-1} - v_t*(w.w)
//             a_t = v_t + q_t;  q_{t-1} = c_t + a*q_t
// Block then writes v_seq, z_seq (coalesced) into d_out and a into g_A.
// ---------------------------------------------------------------------------
__global__ __launch_bounds__(128) void k_scan(const float* __restrict__ w,
                                              float* __restrict__ out) {
    __shared__ float sv[TT];   // holds s, then v in place
    __shared__ float sa[TT];   // a_t
    __shared__ float s_ww;
    const int tid = threadIdx.x;
    const int b   = blockIdx.x;

    // cooperative load of this batch's S row (contiguous, coalesced)
    const float* srow = g_S + b * TT;
    for (int t = tid; t < TT; t += 128) sv[t] = srow[t];

    // warp 0 computes w.w concurrently
    if (tid < 32) {
        float ww = 0.0f;
#pragma unroll 8
        for (int i = tid; i < NN; i += 32) ww += w[i] * w[i];
#pragma unroll
        for (int o = 16; o > 0; o >>= 1)
            ww += __shfl_xor_sync(0xFFFFFFFFu, ww, o);
        if (tid == 0) s_ww = ww;
    }
    __syncthreads();

    if (tid == 0) {
        const float ww = s_ww;

        // ---- forward scan (smem-resident) ----
        float v = 0.0f, v2 = 0.0f;
#pragma unroll 8
        for (int t = 0; t < TT; t++) {
            const float s  = sv[t];
            const float pv = v;
            v = fmaf(ALPHA, v, s);       // chain: FFMA(4)
            if (pv > VTH) v -= VTH;      // FSETP(13) overlaps FFMA; +FADD(4)
            sv[t] = v;
            v2 += v * v;                 // off-chain
        }
        g_V2[b] = v2;

        // ---- backward scan: reconstruct c_t from v values ----
        float q = 0.0f;
#pragma unroll 8
        for (int t = TT - 1; t > 0; t--) {
            const float vt = sv[t];
            const float vp = sv[t - 1];
            sa[t] = vt + q;                              // a_t = v_t + q_t
            float c = vt - ALPHA * vp - vt * ww;         // s_t - v_t*ww ...
            if (vp > VTH) c += VTH;                      // ... + VTH*z_{t-1}
            q = fmaf(ALPHA, q, c);                       // q_{t-1}
        }
        sa[0] = sv[0] + q;
    }
    __syncthreads();

    // coalesced epilogue: v_seq, z_seq, a
    float* vout = out + b * TT;
    float* zout = out + BB * TT + b * TT;
    float* aout = g_A + b * TT;
    for (int t = tid; t < TT; t += 128) {
        const float v = sv[t];
        vout[t] = v;
        zout[t] = (v > VTH) ? 1.0f : 0.0f;
        aout[t] = sa[t];
    }
}

// ---------------------------------------------------------------------------
// Kernel 3: grad[b,n] = sum_t a[b,t] * x[b,t,n]  -  V2[b] * w[n]
// grid = (4 column-chunks, 32 batches), block = 128 threads (float4 each,
// 512 columns per CTA). Streams 1024 rows with a_t broadcast from smem.
// ---------------------------------------------------------------------------
__global__ __launch_bounds__(128) void k_grad(const float4* __restrict__ X4,
                                              const float4* __restrict__ W4,
                                              float* __restrict__ out) {
    __shared__ float sa[TT];
    const int tid   = threadIdx.x;   // 0..127
    const int chunk = blockIdx.x;    // 0..3
    const int b     = blockIdx.y;    // 0..31

    for (int t = tid; t < TT; t += 128) sa[t] = g_A[b * TT + t];
    __syncthreads();

    const int col4 = chunk * 128 + tid;  // float4 column index, 0..511
    const float4* xp = X4 + (size_t)b * TT * (NN / 4) + col4;

    float4 acc = make_float4(0.f, 0.f, 0.f, 0.f);
#pragma unroll 8
    for (int t = 0; t < TT; t++) {
        const float a = sa[t];
        const float4 x = xp[(size_t)t * (NN / 4)];
        acc.x += a * x.x;
        acc.y += a * x.y;
        acc.z += a * x.z;
        acc.w += a * x.w;
    }

    const float v2 = g_V2[b];
    const float4 wv = W4[col4];
    float4 g;
    g.x = acc.x - v2 * wv.x;
    g.y = acc.y - v2 * wv.y;
    g.z = acc.z - v2 * wv.z;
    g.w = acc.w - v2 * wv.w;

    float4* gout = (float4*)(out + 2 * BB * TT);
    gout[(size_t)b * (NN / 4) + col4] = g;
}

// ---------------------------------------------------------------------------
extern "C" void kernel_launch(void* const* d_in, const int* in_sizes, int n_in,
                              void* d_out, int out_size) {
    const float* x = (const float*)d_in[0];
    const float* w = (const float*)d_in[1];
    // Defensive: metadata order should be (x, w); swap if sizes say otherwise.
    if (n_in >= 2 && in_sizes[0] == NN && in_sizes[1] != NN) {
        const float* tmp = x; x = w; w = tmp;
    }
    float* out = (float*)d_out;

    k_gemv<<<4096, 128>>>((const float4*)x, (const float4*)w);
    k_scan<<<32, 128>>>(w, out);
    k_grad<<<dim3(4, 32), 128>>>((const float4*)x, (const float4*)w, out);
}

// round 5
// speedup vs baseline: 6.4418x; 2.1360x over previous
#include <cuda_runtime.h>

// Problem constants (B=32, T=1024, N=2048)
#define BB 32
#define TT 1024
#define NN 2048
#define ALPHA 0.995f
#define VTH   2.0f
#define SEG   8           // T-segments for k_grad_partial
#define TSEG  (TT / SEG)  // 128 timesteps per segment

// Scratch (device globals -- no allocation allowed)
__device__ float g_S[BB * TT];          // S[b][t] = x[b,t,:] . w
__device__ float g_A[BB * TT];          // a[b][t] = v_t + q_t
__device__ float g_V2[BB];              // sum of v_t^2 per batch
__device__ float g_P[SEG * BB * NN];    // partial grads [seg][b][n] (2 MB)

// ---------------------------------------------------------------------------
// Kernel 1: S[b,t] = x[b,t,:] . w   (row dot products), [b][t] layout.
// grid = 4096 CTAs x 8 rows each, block = 128 threads, float4 loads.
// Measured ~6.15 TB/s (near LTS cap) -- unchanged.
// ---------------------------------------------------------------------------
__global__ __launch_bounds__(128) void k_gemv(const float4* __restrict__ X4,
                                              const float4* __restrict__ W4) {
    __shared__ float red[4];
    const int tid = threadIdx.x;

    const float4 w0 = W4[tid];
    const float4 w1 = W4[128 + tid];
    const float4 w2 = W4[256 + tid];
    const float4 w3 = W4[384 + tid];

    const int base_row = blockIdx.x * 8;

#pragma unroll 1
    for (int rr = 0; rr < 8; rr++) {
        const int r = base_row + rr;                 // r = b*TT + t
        const float4* xp = X4 + (size_t)r * (NN / 4);
        const float4 x0 = xp[tid];
        const float4 x1 = xp[128 + tid];
        const float4 x2 = xp[256 + tid];
        const float4 x3 = xp[384 + tid];

        float s = x0.x * w0.x + x0.y * w0.y + x0.z * w0.z + x0.w * w0.w
                + x1.x * w1.x + x1.y * w1.y + x1.z * w1.z + x1.w * w1.w
                + x2.x * w2.x + x2.y * w2.y + x2.z * w2.z + x2.w * w2.w
                + x3.x * w3.x + x3.y * w3.y + x3.z * w3.z + x3.w * w3.w;

#pragma unroll
        for (int o = 16; o > 0; o >>= 1)
            s += __shfl_xor_sync(0xFFFFFFFFu, s, o);
        if ((tid & 31) == 0) red[tid >> 5] = s;
        __syncthreads();
        if (tid == 0) g_S[r] = red[0] + red[1] + red[2] + red[3];
        __syncthreads();
    }
}

// ---------------------------------------------------------------------------
// Kernel 2: per-batch scalar scans, one CTA per batch, scan from SMEM.
// ---------------------------------------------------------------------------
__global__ __launch_bounds__(128) void k_scan(const float* __restrict__ w,
                                              float* __restrict__ out) {
    __shared__ float sv[TT];   // holds s, then v in place
    __shared__ float sa[TT];   // a_t
    __shared__ float s_ww;
    const int tid = threadIdx.x;
    const int b   = blockIdx.x;

    const float* srow = g_S + b * TT;
    for (int t = tid; t < TT; t += 128) sv[t] = srow[t];

    if (tid < 32) {
        float ww = 0.0f;
#pragma unroll 8
        for (int i = tid; i < NN; i += 32) ww += w[i] * w[i];
#pragma unroll
        for (int o = 16; o > 0; o >>= 1)
            ww += __shfl_xor_sync(0xFFFFFFFFu, ww, o);
        if (tid == 0) s_ww = ww;
    }
    __syncthreads();

    if (tid == 0) {
        const float ww = s_ww;

        // ---- forward scan ----
        float v = 0.0f, v2 = 0.0f;
#pragma unroll 8
        for (int t = 0; t < TT; t++) {
            const float s  = sv[t];
            const float pv = v;
            v = fmaf(ALPHA, v, s);
            if (pv > VTH) v -= VTH;
            sv[t] = v;
            v2 += v * v;
        }
        g_V2[b] = v2;

        // ---- backward scan: c_t reconstructed from v values ----
        float q = 0.0f;
#pragma unroll 8
        for (int t = TT - 1; t > 0; t--) {
            const float vt = sv[t];
            const float vp = sv[t - 1];
            sa[t] = vt + q;
            float c = vt - ALPHA * vp - vt * ww;
            if (vp > VTH) c += VTH;
            q = fmaf(ALPHA, q, c);
        }
        sa[0] = sv[0] + q;
    }
    __syncthreads();

    float* vout = out + b * TT;
    float* zout = out + BB * TT + b * TT;
    float* aout = g_A + b * TT;
    for (int t = tid; t < TT; t += 128) {
        const float v = sv[t];
        vout[t] = v;
        zout[t] = (v > VTH) ? 1.0f : 0.0f;
        aout[t] = sa[t];
    }
}

// ---------------------------------------------------------------------------
// Kernel 3a: partial grad over a T-segment.
//   P[seg][b][n] = sum_{t in seg} a[b,t] * x[b,t,n]
// grid = (4 chunks, 32 b, SEG), block = 128 threads (one float4 column each).
// 1024 CTAs -> ~7/SM, ~16 MB in flight -> DRAM-bound.
// ---------------------------------------------------------------------------
__global__ __launch_bounds__(128) void k_grad_partial(const float4* __restrict__ X4) {
    __shared__ float sa[TSEG];
    const int tid   = threadIdx.x;   // 0..127
    const int chunk = blockIdx.x;    // 0..3
    const int b     = blockIdx.y;    // 0..31
    const int seg   = blockIdx.z;    // 0..SEG-1
    const int t0    = seg * TSEG;

    if (tid < TSEG) sa[tid] = g_A[b * TT + t0 + tid];
    __syncthreads();

    const int col4 = chunk * 128 + tid;  // float4 column index, 0..511
    const float4* xp = X4 + ((size_t)b * TT + t0) * (NN / 4) + col4;

    float4 acc = make_float4(0.f, 0.f, 0.f, 0.f);
#pragma unroll 8
    for (int t = 0; t < TSEG; t++) {
        const float a = sa[t];
        const float4 x = xp[(size_t)t * (NN / 4)];
        acc.x += a * x.x;
        acc.y += a * x.y;
        acc.z += a * x.z;
        acc.w += a * x.w;
    }

    float4* pp = (float4*)g_P;
    pp[((size_t)seg * BB + b) * (NN / 4) + col4] = acc;
}

// ---------------------------------------------------------------------------
// Kernel 3b: reduce partials + w-correction.
//   grad[b,n] = sum_seg P[seg][b][n] - V2[b]*w[n]
// 16384 float4 lanes total: grid 128, block 128.
// ---------------------------------------------------------------------------
__global__ __launch_bounds__(128) void k_grad_reduce(const float4* __restrict__ W4,
                                                     float* __restrict__ out) {
    const int i = blockIdx.x * 128 + threadIdx.x;   // 0..16383 = b*512 + col4
    const int b    = i >> 9;
    const int col4 = i & 511;

    const float4* pp = (const float4*)g_P;
    float4 acc = make_float4(0.f, 0.f, 0.f, 0.f);
#pragma unroll
    for (int seg = 0; seg < SEG; seg++) {
        const float4 p = pp[((size_t)seg * BB + b) * (NN / 4) + col4];
        acc.x += p.x; acc.y += p.y; acc.z += p.z; acc.w += p.w;
    }

    const float v2 = g_V2[b];
    const float4 wv = W4[col4];
    float4 g;
    g.x = acc.x - v2 * wv.x;
    g.y = acc.y - v2 * wv.y;
    g.z = acc.z - v2 * wv.z;
    g.w = acc.w - v2 * wv.w;

    float4* gout = (float4*)(out + 2 * BB * TT);
    gout[(size_t)b * (NN / 4) + col4] = g;
}

// ---------------------------------------------------------------------------
extern "C" void kernel_launch(void* const* d_in, const int* in_sizes, int n_in,
                              void* d_out, int out_size) {
    const float* x = (const float*)d_in[0];
    const float* w = (const float*)d_in[1];
    if (n_in >= 2 && in_sizes[0] == NN && in_sizes[1] != NN) {
        const float* tmp = x; x = w; w = tmp;
    }
    float* out = (float*)d_out;

    k_gemv<<<4096, 128>>>((const float4*)x, (const float4*)w);
    k_scan<<<32, 128>>>(w, out);
    k_grad_partial<<<dim3(4, 32, SEG), 128>>>((const float4*)x);
    k_grad_reduce<<<128, 128>>>((const float4*)w, out);
}